// round 4
// baseline (speedup 1.0000x reference)
#include <cuda_runtime.h>
#include <cuda_fp16.h>
#include <cstdint>
#include <cstddef>

// ----------------------------------------------------------------------------
// ThickConv2d as one fp16 mma.sync GEMM (sm_100 non-'a' target: no tcgen05):
//   A (im2col of x, fp16) [8192 x 1152] @ W1^T (fp16) [1152 x 8192]
//   fp32 accum -> epilogue: +b1, leaky(0.1), 64-wide w2 contraction, +b2
// ----------------------------------------------------------------------------

#define P_TOT   8192          // B*H*W
#define K_TOT   1152          // Cin*9
#define N_TOT   8192          // OUT_CH*MID_CH
#define BM      128
#define BN      128           // = 2 output channels x 64 mid
#define BK      64            // halves per chunk (128B rows)
#define NCH     18            // 1152/64
#define STAGES  3
#define STAGE_BYTES (BM*128 + BN*128)            // 32 KB
#define CONST_OFF   (STAGES*STAGE_BYTES)         // 98304
#define SMEM_BYTES  (CONST_OFF + 512 + 512 + 64 + 2048)

__device__ __half g_A[(size_t)P_TOT * K_TOT];
__device__ __half g_B[(size_t)N_TOT * K_TOT];

__device__ __forceinline__ uint32_t smem_u32(const void* p) {
    uint32_t a;
    asm("{ .reg .u64 t; cvta.to.shared.u64 t, %1; cvt.u32.u64 %0, t; }"
        : "=r"(a) : "l"(p));
    return a;
}

__device__ __forceinline__ void cp16(uint32_t s, const void* g) {
    asm volatile("cp.async.cg.shared.global [%0], [%1], 16;"
                 :: "r"(s), "l"(g) : "memory");
}

#define CP_COMMIT() asm volatile("cp.async.commit_group;" ::: "memory")
#define CP_WAIT2()  asm volatile("cp.async.wait_group 2;" ::: "memory")

__device__ __forceinline__ void ldm4(uint32_t* r, uint32_t addr) {
    asm volatile("ldmatrix.sync.aligned.m8n8.x4.shared.b16 {%0,%1,%2,%3}, [%4];"
                 : "=r"(r[0]), "=r"(r[1]), "=r"(r[2]), "=r"(r[3]) : "r"(addr));
}

__device__ __forceinline__ void mma16816(float* c, const uint32_t* a,
                                         const uint32_t* b) {
    asm volatile(
        "mma.sync.aligned.m16n8k16.row.col.f32.f16.f16.f32 "
        "{%0,%1,%2,%3}, {%4,%5,%6,%7}, {%8,%9}, {%0,%1,%2,%3};"
        : "+f"(c[0]), "+f"(c[1]), "+f"(c[2]), "+f"(c[3])
        : "r"(a[0]), "r"(a[1]), "r"(a[2]), "r"(a[3]), "r"(b[0]), "r"(b[1]));
}

// ----------------------------------------------------------------------------
// Prep (single kernel): fp16 weights + fp16 im2col of x
// k index = c*9 + ky*3 + kx (matches w1's [*, Cin, 3, 3] layout)
// ----------------------------------------------------------------------------
__global__ void prep_kernel(const float* __restrict__ x,
                            const float* __restrict__ w1) {
    int gid = blockIdx.x * 256 + threadIdx.x;
    const int nElems = P_TOT * K_TOT;
    if (gid < nElems) {
        // weights half
        g_B[gid] = __float2half_rn(w1[gid]);
    }
    gid -= nElems;
    if (gid < 0 || gid >= nElems) return;
    int p  = gid / K_TOT;
    int k  = gid - p * K_TOT;
    int c  = k / 9;
    int r9 = k - c * 9;
    int ky = r9 / 3;
    int kx = r9 - ky * 3;
    int b  = p >> 10;
    int y  = (p >> 5) & 31;
    int xx = p & 31;
    int iy = y + ky - 1;
    int ix = xx + kx - 1;
    float v = 0.0f;
    if ((unsigned)iy < 32u && (unsigned)ix < 32u)
        v = x[(((b << 7) + c) << 10) + (iy << 5) + ix];
    g_A[gid] = __float2half_rn(v);
}

// ----------------------------------------------------------------------------
// GEMM: 256 threads, 8 warps (2 row-warps x 4 col-warps), warp tile 64x32.
// ----------------------------------------------------------------------------
__global__ __launch_bounds__(256, 2)
void gemm_kernel(const float* __restrict__ b1, const float* __restrict__ w2,
                 const float* __restrict__ b2, float* __restrict__ out) {
    extern __shared__ char smem[];
    const uint32_t sb = smem_u32(smem);
    const int tid = threadIdx.x;
    const int wid = tid >> 5;
    const int lid = tid & 31;
    const int wr  = wid >> 2;        // 0..1  (rows wr*64..+63)
    const int wc  = wid & 3;         // 0..3  (cols wc*32..+31)
    const int ptile = blockIdx.x & 63;
    const int ntile = blockIdx.x >> 6;

    float* b1s  = (float*)(smem + CONST_OFF);             // 128
    float* w2f  = (float*)(smem + CONST_OFF + 512);       // 128
    float* b2f  = (float*)(smem + CONST_OFF + 1024);      // 2
    float* part = (float*)(smem + CONST_OFF + 1088);      // [4][128]

    if (tid < 128) {
        b1s[tid] = b1[ntile * 128 + tid];
        w2f[tid] = w2[ntile * 128 + tid];   // w2 flat [o*64+m]; 2 chans contiguous
    }
    if (tid < 2) b2f[tid] = b2[ntile * 2 + tid];

    const __half* Ag = g_A + (size_t)(ptile * BM) * K_TOT;
    const __half* Bg = g_B + (size_t)(ntile * BN) * K_TOT;
    const int r8 = tid >> 3, c8 = tid & 7;                 // load mapping

    auto load_stage = [&](int ch, int slot) {
        const uint32_t sA = sb + slot * STAGE_BYTES;
        const uint32_t sB = sA + BM * 128;
        const __half* As = Ag + ch * BK;
        const __half* Bs = Bg + ch * BK;
        #pragma unroll
        for (int i = 0; i < 4; i++) {
            int r = r8 + i * 32;                           // 0..127
            cp16(sA + r * 128 + (((c8 ^ (r & 7))) << 4),
                 As + (size_t)r * K_TOT + c8 * 8);
        }
        #pragma unroll
        for (int i = 0; i < 4; i++) {
            int r = r8 + i * 32;
            cp16(sB + r * 128 + (((c8 ^ (r & 7))) << 4),
                 Bs + (size_t)r * K_TOT + c8 * 8);
        }
    };

    load_stage(0, 0); CP_COMMIT();
    load_stage(1, 1); CP_COMMIT();

    float acc[4][4][4];
    #pragma unroll
    for (int i = 0; i < 4; i++)
        #pragma unroll
        for (int j = 0; j < 4; j++)
            #pragma unroll
            for (int e = 0; e < 4; e++) acc[i][j][e] = 0.0f;

    for (int ch = 0; ch < NCH; ch++) {
        if (ch + 2 < NCH) load_stage(ch + 2, (ch + 2) % STAGES);
        CP_COMMIT();
        CP_WAIT2();
        __syncthreads();

        const uint32_t aBase = sb + (ch % STAGES) * STAGE_BYTES;
        const uint32_t bBase = aBase + BM * 128;

        #pragma unroll
        for (int ks = 0; ks < 4; ks++) {
            uint32_t a[4][4];
            #pragma unroll
            for (int mf = 0; mf < 4; mf++) {
                int ra = wr * 64 + mf * 16 + (lid & 15);
                uint32_t addr = aBase + ra * 128 +
                    ((((ks << 1) + (lid >> 4)) ^ (ra & 7)) << 4);
                ldm4(a[mf], addr);
            }
            uint32_t b[4][2];
            #pragma unroll
            for (int nf2 = 0; nf2 < 2; nf2++) {
                int rb = wc * 32 + nf2 * 16 + (lid & 7) + ((lid >> 4) << 3);
                uint32_t addr = bBase + rb * 128 +
                    ((((ks << 1) + ((lid >> 3) & 1)) ^ (rb & 7)) << 4);
                uint32_t t[4];
                ldm4(t, addr);
                b[nf2 * 2][0] = t[0]; b[nf2 * 2][1] = t[1];
                b[nf2 * 2 + 1][0] = t[2]; b[nf2 * 2 + 1][1] = t[3];
            }
            #pragma unroll
            for (int mf = 0; mf < 4; mf++)
                #pragma unroll
                for (int nf = 0; nf < 4; nf++)
                    mma16816(acc[mf][nf], a[mf], b[nf]);
        }
        __syncthreads();
    }

    // ---------------- epilogue ----------------
    // acc[mf][nf][e]: row = wr*64+mf*16+(lid>>2)+8*(e>>1); col = wc*32+nf*8+(lid&3)*2+(e&1)
    #pragma unroll
    for (int mf = 0; mf < 4; mf++) {
        #pragma unroll
        for (int rh = 0; rh < 2; rh++) {
            float p = 0.0f;
            #pragma unroll
            for (int nf = 0; nf < 4; nf++) {
                #pragma unroll
                for (int cc = 0; cc < 2; cc++) {
                    int nt = wc * 32 + nf * 8 + (lid & 3) * 2 + cc;
                    float v = acc[mf][nf][rh * 2 + cc] + b1s[nt];
                    v = (v < 0.0f) ? 0.1f * v : v;
                    p = fmaf(w2f[nt], v, p);
                }
            }
            p += __shfl_xor_sync(0xFFFFFFFFu, p, 1);
            p += __shfl_xor_sync(0xFFFFFFFFu, p, 2);
            if ((lid & 3) == 0)
                part[wc * 128 + wr * 64 + mf * 16 + (lid >> 2) + rh * 8] = p;
        }
    }
    __syncthreads();

    {
        int rowp = tid & 127;
        int chn  = tid >> 7;                 // 0..1
        float v = part[(chn * 2) * 128 + rowp] + part[(chn * 2 + 1) * 128 + rowp]
                + b2f[chn];
        int p  = ptile * BM + rowp;
        int bN = p >> 10;
        int hw = p & 1023;
        int o  = ntile * 2 + chn;
        out[(size_t)(bN * 128 + o) * 1024 + hw] = v;
    }
}

// ----------------------------------------------------------------------------
extern "C" void kernel_launch(void* const* d_in, const int* in_sizes, int n_in,
                              void* d_out, int out_size) {
    const float* x  = (const float*)d_in[0];
    const float* w1 = (const float*)d_in[1];
    const float* b1 = (const float*)d_in[2];
    const float* w2 = (const float*)d_in[3];
    const float* b2 = (const float*)d_in[4];
    float* out = (float*)d_out;

    cudaFuncSetAttribute(gemm_kernel, cudaFuncAttributeMaxDynamicSharedMemorySize,
                         SMEM_BYTES);

    const int nElems = P_TOT * K_TOT;
    const int blocks = (2 * nElems + 255) / 256;
    prep_kernel<<<blocks, 256>>>(x, w1);
    gemm_kernel<<<64 * 64, 256, SMEM_BYTES>>>(b1, w2, b2, out);
}